// round 3
// baseline (speedup 1.0000x reference)
#include <cuda_runtime.h>
#include <math.h>

#define N_ 8192
#define K_ 64
#define CARDN 64
#define BIGF 1e9f
#define EPSV 0.01f
#define INV_EPS 100.0f
#define LOG64 4.1588830833596715f
#define SINK_ITERS 300

// ---------------- device scratch (no allocations allowed) ----------------
__device__ float g_T[N_ * K_];      // adj @ S   [8192,64]
__device__ float g_C[K_ * K_];      // S^T (adj S) [64,64]
__device__ float g_dgm0[CARDN * 2];
__device__ float g_dgm1[CARDN * 2];
__device__ float g_loss[4];

// ---------------- packed fp32x2 helpers (Blackwell fp32 2x pipe) ----------------
#define PACK2(out, lo, hi) \
    asm("mov.b64 %0, {%1, %2};" : "=l"(out) : "r"(__float_as_uint(lo)), "r"(__float_as_uint(hi)))
#define FMA2(d, a, b) \
    asm("fma.rn.f32x2 %0, %1, %2, %0;" : "+l"(d) : "l"(a), "l"(b))
#define UNPACK2(lo, hi, in) do { \
    unsigned _ulo, _uhi; \
    asm("mov.b64 {%0, %1}, %2;" : "=r"(_ulo), "=r"(_uhi) : "l"(in)); \
    lo = __uint_as_float(_ulo); hi = __uint_as_float(_uhi); } while (0)

// ================= GEMM1: T = adj @ S  (8192x8192 * 8192x64) =================
// 128 blocks x 256 threads; BM=64, BN=64, BK=32; each thread 4x4 outputs,
// accumulated as 8 packed f32x2 to use the doubled fp32 pipe.
__global__ void __launch_bounds__(256) gemm1_kernel(const float* __restrict__ A,
                                                    const float* __restrict__ S) {
    __shared__ float As[32][68];  // As[k][m]
    __shared__ float Bs[32][68];  // Bs[k][n]
    int tid = threadIdx.x;
    int m0 = blockIdx.x * 64;
    int tx = tid & 15, ty = tid >> 4;
    unsigned long long acc[4][2];
#pragma unroll
    for (int r = 0; r < 4; r++) { acc[r][0] = 0ull; acc[r][1] = 0ull; }

    for (int k0 = 0; k0 < N_; k0 += 32) {
#pragma unroll
        for (int i = 0; i < 2; i++) {
            int idx = tid + i * 256;          // 0..511
            int m = idx >> 3, kq = idx & 7;   // m 0..63, kq 0..7 (float4 along k)
            float4 v = *(const float4*)(A + (size_t)(m0 + m) * N_ + k0 + kq * 4);
            As[kq * 4 + 0][m] = v.x; As[kq * 4 + 1][m] = v.y;
            As[kq * 4 + 2][m] = v.z; As[kq * 4 + 3][m] = v.w;
        }
#pragma unroll
        for (int i = 0; i < 2; i++) {
            int idx = tid + i * 256;
            int kr = idx >> 4, nq = idx & 15;
            *(float4*)&Bs[kr][nq * 4] = *(const float4*)(S + (size_t)(k0 + kr) * 64 + nq * 4);
        }
        __syncthreads();
#pragma unroll
        for (int kk = 0; kk < 32; kk++) {
            float4 av = *(float4*)&As[kk][ty * 4];
            float4 bv = *(float4*)&Bs[kk][tx * 4];
            unsigned long long b01, b23;
            PACK2(b01, bv.x, bv.y);
            PACK2(b23, bv.z, bv.w);
            float am[4] = {av.x, av.y, av.z, av.w};
#pragma unroll
            for (int r = 0; r < 4; r++) {
                unsigned long long aa;
                PACK2(aa, am[r], am[r]);
                FMA2(acc[r][0], aa, b01);
                FMA2(acc[r][1], aa, b23);
            }
        }
        __syncthreads();
    }
#pragma unroll
    for (int r = 0; r < 4; r++) {
        float o0, o1, o2, o3;
        UNPACK2(o0, o1, acc[r][0]);
        UNPACK2(o2, o3, acc[r][1]);
        *(float4*)&g_T[(size_t)(m0 + ty * 4 + r) * 64 + tx * 4] = make_float4(o0, o1, o2, o3);
    }
}

// ================= GEMM2: C = S^T @ T  (64x8192 * 8192x64) =================
// 64 blocks (one output row each); T (2MB) is L2-resident so re-reads are cheap.
__global__ void __launch_bounds__(256) gemm2_kernel(const float* __restrict__ S) {
    int b = blockIdx.x;
    int tid = threadIdx.x;
    int j = tid & 63, slice = tid >> 6;
    float a0 = 0.f, a1 = 0.f, a2 = 0.f, a3 = 0.f;
    for (int k = slice; k < N_; k += 16) {
        a0 += S[(k +  0) * 64 + b] * g_T[(k +  0) * 64 + j];
        a1 += S[(k +  4) * 64 + b] * g_T[(k +  4) * 64 + j];
        a2 += S[(k +  8) * 64 + b] * g_T[(k +  8) * 64 + j];
        a3 += S[(k + 12) * 64 + b] * g_T[(k + 12) * 64 + j];
    }
    __shared__ float red[256];
    red[tid] = (a0 + a1) + (a2 + a3);
    __syncthreads();
    if (tid < 64)
        g_C[b * 64 + tid] = red[tid] + red[tid + 64] + red[tid + 128] + red[tid + 192];
}

// ========== finalize D + Prim MST + dgm0 + triangle deaths + top-64 dgm1 ==========
__global__ void __launch_bounds__(1024) topo_kernel() {
    __shared__ float Dsm[64][65];
    __shared__ float pers[4096];
    __shared__ float wred[32];
    __shared__ float ws_s[63];
    __shared__ int us_s[63], vs_s[63];
    __shared__ float mind[64];
    __shared__ int minu[64];
    __shared__ unsigned long long msk[64];
    __shared__ float mx_s;
    __shared__ float bv_s[32];
    __shared__ int bi_s[32];

    int tid = threadIdx.x;
    int lane = tid & 31, warp = tid >> 5;

    // 1) symmetrize + global max
    float lmax = -1e30f;
#pragma unroll
    for (int w = 0; w < 4; w++) {
        int p = tid + w * 1024;
        int i = p >> 6, jj = p & 63;
        float cs = 0.5f * (g_C[i * 64 + jj] + g_C[jj * 64 + i]);
        Dsm[i][jj] = cs;
        lmax = fmaxf(lmax, cs);
    }
    for (int o = 16; o; o >>= 1) lmax = fmaxf(lmax, __shfl_xor_sync(~0u, lmax, o));
    if (lane == 0) wred[warp] = lmax;
    __syncthreads();
    if (warp == 0) {
        float v = wred[lane];
        for (int o = 16; o; o >>= 1) v = fmaxf(v, __shfl_xor_sync(~0u, v, o));
        if (lane == 0) mx_s = v;
    }
    __syncthreads();
    float inv = 1.0f / (mx_s + 1e-12f);
#pragma unroll
    for (int w = 0; w < 4; w++) {
        int p = tid + w * 1024;
        int i = p >> 6, jj = p & 63;
        float d = 1.0f - Dsm[i][jj] * inv;
        Dsm[i][jj] = (i == jj) ? 0.0f : d;
    }
    __syncthreads();

    // 2) Prim MST on warp 0 (63 sequential steps)
    if (warp == 0) {
        unsigned long long intree = 1ull;
#pragma unroll
        for (int h = 0; h < 2; h++) {
            int v = lane + 32 * h;
            mind[v] = Dsm[0][v];
            minu[v] = 0;
        }
        __syncwarp();
        for (int step = 0; step < 63; step++) {
            float bval = BIGF; int bidx = 64;
#pragma unroll
            for (int h = 0; h < 2; h++) {
                int v = lane + 32 * h;
                float mv = ((intree >> v) & 1ull) ? BIGF : mind[v];
                if (mv < bval || (mv == bval && v < bidx)) { bval = mv; bidx = v; }
            }
            for (int o = 16; o; o >>= 1) {
                float ov = __shfl_xor_sync(~0u, bval, o);
                int oi = __shfl_xor_sync(~0u, bidx, o);
                if (ov < bval || (ov == bval && oi < bidx)) { bval = ov; bidx = oi; }
            }
            int vstar = bidx;
            if (lane == 0) { ws_s[step] = bval; us_s[step] = minu[vstar]; vs_s[step] = vstar; }
            intree |= (1ull << vstar);
#pragma unroll
            for (int h = 0; h < 2; h++) {
                int v = lane + 32 * h;
                float dv = Dsm[vstar][v];
                if (dv < mind[v]) { mind[v] = dv; minu[v] = vstar; }
            }
            __syncwarp();
        }
    }
    __syncthreads();

    // 3) dgm0 (order irrelevant for W1) + MST mask
    if (tid < 64) {
        g_dgm0[2 * tid] = 0.0f;
        g_dgm0[2 * tid + 1] = (tid < 63) ? ws_s[tid] : 0.0f;
        msk[tid] = 0ull;
    }
    __syncthreads();
    if (tid < 63) {
        atomicOr(&msk[us_s[tid]], 1ull << vs_s[tid]);
        atomicOr(&msk[vs_s[tid]], 1ull << us_s[tid]);
    }
    __syncthreads();

    // 4) persistence of 1-cycles: death = max(Dij, min_{k!=i,j} max(Dik, Djk))
#pragma unroll
    for (int w = 0; w < 4; w++) {
        int p = tid + w * 1024;
        int i = p >> 6, jj = p & 63;
        float pe = -1.0f;
        if (i < jj && !((msk[i] >> jj) & 1ull)) {
            float mm = BIGF;
#pragma unroll
            for (int k = 0; k < 64; k++) {
                float t = fmaxf(Dsm[i][k], Dsm[jj][k]);
                if (k != i && k != jj) mm = fminf(mm, t);
            }
            float dij = Dsm[i][jj];
            pe = fmaxf(dij, mm) - dij;
        }
        pers[p] = pe;
    }
    __syncthreads();

    // 5) top-64 by (pers, lowest flat index) -> dgm1
    for (int r = 0; r < 64; r++) {
        float bval = -3e9f; int bidx = 1 << 30;
#pragma unroll
        for (int w = 0; w < 4; w++) {
            int p = tid + w * 1024;
            float v = pers[p];
            if (v > bval || (v == bval && p < bidx)) { bval = v; bidx = p; }
        }
        for (int o = 16; o; o >>= 1) {
            float ov = __shfl_xor_sync(~0u, bval, o);
            int oi = __shfl_xor_sync(~0u, bidx, o);
            if (ov > bval || (ov == bval && oi < bidx)) { bval = ov; bidx = oi; }
        }
        if (lane == 0) { bv_s[warp] = bval; bi_s[warp] = bidx; }
        __syncthreads();
        if (warp == 0) {
            float v2 = bv_s[lane]; int i2 = bi_s[lane];
            for (int o = 16; o; o >>= 1) {
                float ov = __shfl_xor_sync(~0u, v2, o);
                int oi = __shfl_xor_sync(~0u, i2, o);
                if (ov > v2 || (ov == v2 && oi < i2)) { v2 = ov; i2 = oi; }
            }
            if (lane == 0) {
                int i = i2 >> 6, jj = i2 & 63;
                float b = 0.f, d = 0.f;
                if (v2 > 0.f) { b = Dsm[i][jj]; d = b + v2; }
                g_dgm1[2 * r] = b;
                g_dgm1[2 * r + 1] = d;
                pers[i2] = -4e9f;  // remove from future rounds
            }
        }
        __syncthreads();
    }
}

// ================= Sinkhorn W1: 4 independent blocks =================
// 65x65 cost in smem (row-major + transposed); 4 threads per row; 300 iters.
__global__ void __launch_bounds__(288) sinkhorn_kernel(const float* __restrict__ Yb0,
                                                       const float* __restrict__ Yb1,
                                                       const float* __restrict__ Yn0,
                                                       const float* __restrict__ Yn1) {
    __shared__ float Cm[65][66];
    __shared__ float Ct[65][66];
    __shared__ float fsh[65], gsh[65];
    __shared__ float rsum[9];

    int b = blockIdx.x;
    const float* X = (b & 1) ? g_dgm1 : g_dgm0;
    const float* Y = (b == 0) ? Yb0 : (b == 1) ? Yb1 : (b == 2) ? Yn0 : Yn1;
    int t = threadIdx.x;

    for (int idx = t; idx < 65 * 65; idx += 288) {
        int i = idx / 65, j = idx % 65;
        float v;
        if (i < 64 && j < 64)
            v = fmaxf(fabsf(X[2 * i] - Y[2 * j]), fabsf(X[2 * i + 1] - Y[2 * j + 1]));
        else if (i < 64)
            v = 0.5f * (X[2 * i + 1] - X[2 * i]);
        else if (j < 64)
            v = 0.5f * (Y[2 * j + 1] - Y[2 * j]);
        else
            v = 0.f;
        Cm[i][j] = v;
        Ct[j][i] = v;
    }
    if (t < 65) { fsh[t] = 0.f; gsh[t] = 0.f; }
    __syncthreads();

    int row = t >> 2; if (row > 64) row = 64;
    int sub = t & 3;
    bool lead = (t < 260) && (sub == 0);
    float la = (row == 64) ? LOG64 : 0.f;

    for (int it = 0; it < SINK_ITERS; it++) {
        // f[i] = eps*(loga - LSE_j((g[j]-C[i,j])/eps))
        {
            float xs[17], m = -1e30f;
#pragma unroll
            for (int s2 = 0; s2 < 17; s2++) {
                int j = sub + 4 * s2;
                float x = (j < 65) ? (gsh[j] - Cm[row][j]) * INV_EPS : -1e38f;
                xs[s2] = x; m = fmaxf(m, x);
            }
            float s = 0.f;
#pragma unroll
            for (int s2 = 0; s2 < 17; s2++) s += __expf(xs[s2] - m);
#pragma unroll
            for (int o = 1; o < 4; o <<= 1) {
                float om = __shfl_xor_sync(~0u, m, o);
                float os = __shfl_xor_sync(~0u, s, o);
                float nm = fmaxf(m, om);
                s = s * __expf(m - nm) + os * __expf(om - nm);
                m = nm;
            }
            if (lead) fsh[row] = EPSV * (la - (m + __logf(s)));
        }
        __syncthreads();
        // g[j] = eps*(logb - LSE_i((f[i]-C[i,j])/eps))
        {
            float xs[17], m = -1e30f;
#pragma unroll
            for (int s2 = 0; s2 < 17; s2++) {
                int i = sub + 4 * s2;
                float x = (i < 65) ? (fsh[i] - Ct[row][i]) * INV_EPS : -1e38f;
                xs[s2] = x; m = fmaxf(m, x);
            }
            float s = 0.f;
#pragma unroll
            for (int s2 = 0; s2 < 17; s2++) s += __expf(xs[s2] - m);
#pragma unroll
            for (int o = 1; o < 4; o <<= 1) {
                float om = __shfl_xor_sync(~0u, m, o);
                float os = __shfl_xor_sync(~0u, s, o);
                float nm = fmaxf(m, om);
                s = s * __expf(m - nm) + os * __expf(om - nm);
                m = nm;
            }
            if (lead) gsh[row] = EPSV * (la - (m + __logf(s)));
        }
        __syncthreads();
    }

    // sum(P * C)
    float acc = 0.f;
    for (int idx = t; idx < 65 * 65; idx += 288) {
        int i = idx / 65, j = idx % 65;
        float c = Cm[i][j];
        acc += __expf((fsh[i] + gsh[j] - c) * INV_EPS) * c;
    }
    for (int o = 16; o; o >>= 1) acc += __shfl_xor_sync(~0u, acc, o);
    int lane = t & 31, warp = t >> 5;
    if (lane == 0) rsum[warp] = acc;
    __syncthreads();
    if (t == 0) {
        float s = 0.f;
        for (int w = 0; w < 9; w++) s += rsum[w];
        g_loss[b] = s;
    }
}

__global__ void final_kernel(float* out) {
    out[0] = 0.1f * (g_loss[0] + g_loss[1] + g_loss[2] + g_loss[3]);
}

// ---------------- launch ----------------
extern "C" void kernel_launch(void* const* d_in, const int* in_sizes, int n_in,
                              void* d_out, int out_size) {
    const float* adj = (const float*)d_in[0];
    const float* S = (const float*)d_in[1];
    gemm1_kernel<<<128, 256>>>(adj, S);
    gemm2_kernel<<<64, 256>>>(S);
    topo_kernel<<<1, 1024>>>();
    sinkhorn_kernel<<<4, 288>>>((const float*)d_in[2], (const float*)d_in[3],
                                (const float*)d_in[4], (const float*)d_in[5]);
    final_kernel<<<1, 1>>>((float*)d_out);
}